// round 8
// baseline (speedup 1.0000x reference)
#include <cuda_runtime.h>
#include <math_constants.h>
#include <cstdint>

// Encoder_46806553591978: per-word softmax-attention pooling over subword spans.
// cp.async double-buffered pipeline: each warp prefetches the NEXT word's two
// emb rows (6KB) into its private smem stage while computing the current word
// from the other stage. Keeps ~12 LDGSTS per warp perpetually in flight so the
// DRAM queues stay full (ncu showed DRAM only ~46% active with burst loads).

#define D_DIM      768
#define ROW_F4     (D_DIM / 4)        // 192 float4 per row
#define PER_LANE   (ROW_F4 / 32)      // 6 float4 per lane per row
#define WARPS_PB   8
#define THREADS_PB (WARPS_PB * 32)
#define GRID_BLKS  304                // 152 SMs * 2 blocks
#define BUF_FLOATS (2 * D_DIM)        // one word = 2 rows = 1536 floats
#define SW_FLOATS  D_DIM

__device__ __forceinline__ void cp16(unsigned int dst, const void* src)
{
    asm volatile("cp.async.cg.shared.global [%0], [%1], 16;"
                 :: "r"(dst), "l"(src));
}
__device__ __forceinline__ void cp_commit()
{
    asm volatile("cp.async.commit_group;");
}
__device__ __forceinline__ void cp_wait1()
{
    asm volatile("cp.async.wait_group 1;");
}

__global__ __launch_bounds__(THREADS_PB)
void encoder_word_pool_kernel(const float* __restrict__ emb,
                              const int*   __restrict__ offs,
                              const float* __restrict__ attn_w,
                              const float* __restrict__ attn_b,
                              float*       __restrict__ out,
                              int n_words)
{
    extern __shared__ float smem[];
    // layout: [0,768) attn_w ; then per-warp double buffers, 2*1536 floats each
    float* sw = smem;

    const int tid  = threadIdx.x;
    const int lane = tid & 31;
    const int warp = tid >> 5;

    for (int i = tid; i < SW_FLOATS / 4; i += THREADS_PB)
        reinterpret_cast<float4*>(sw)[i] =
            reinterpret_cast<const float4*>(attn_w)[i];
    __syncthreads();

    float* buf0 = smem + SW_FLOATS + warp * (2 * BUF_FLOATS);
    float* buf1 = buf0 + BUF_FLOATS;
    const unsigned int b0u = (unsigned int)__cvta_generic_to_shared(buf0);
    const unsigned int b1u = (unsigned int)__cvta_generic_to_shared(buf1);

    const float bias = *attn_b;
    const int stride = gridDim.x * WARPS_PB;
    const int2* __restrict__ offs2 = reinterpret_cast<const int2*>(offs);

    int word = blockIdx.x * WARPS_PB + warp;
    if (word >= n_words) return;

    // ---- prologue: prefetch word 0 into stage 0 ----
    int2 se = offs2[word];
    {
        const float* r0 = emb + (size_t)se.x * D_DIM;
        const float* r1 = emb + (size_t)(se.y - 1) * D_DIM;
        #pragma unroll
        for (int k = 0; k < PER_LANE; ++k) {
            const int fo = (lane + 32 * k) * 4;        // float offset
            cp16(b0u + fo * 4,               r0 + fo);
            cp16(b0u + (D_DIM + fo) * 4,     r1 + fo);
        }
    }
    cp_commit();

    int stage = 0;
    while (true) {
        const int next = word + stride;
        int2 se_n;
        if (next < n_words) {
            se_n = offs2[next];
            const unsigned int bn = stage ? b0u : b1u;
            const float* r0 = emb + (size_t)se_n.x * D_DIM;
            const float* r1 = emb + (size_t)(se_n.y - 1) * D_DIM;
            #pragma unroll
            for (int k = 0; k < PER_LANE; ++k) {
                const int fo = (lane + 32 * k) * 4;
                cp16(bn + fo * 4,           r0 + fo);
                cp16(bn + (D_DIM + fo) * 4, r1 + fo);
            }
        }
        cp_commit();          // commit (possibly empty) group every iteration
        cp_wait1();           // current stage's group is now complete

        float* buf = stage ? buf1 : buf0;
        float4* __restrict__ po =
            reinterpret_cast<float4*>(out + (size_t)word * D_DIM);

        if (se.y - se.x == 2) {
            // ---- fast path: rows in smem, read twice (dot, blend) ----
            const float4* s0 = reinterpret_cast<const float4*>(buf);
            const float4* s1 = s0 + ROW_F4;

            float d0 = 0.f, d1 = 0.f;
            #pragma unroll
            for (int k = 0; k < PER_LANE; ++k) {
                const int idx = lane + 32 * k;
                const float4 wv = reinterpret_cast<const float4*>(sw)[idx];
                const float4 a  = s0[idx];
                const float4 b  = s1[idx];
                d0 += a.x * wv.x + a.y * wv.y + a.z * wv.z + a.w * wv.w;
                d1 += b.x * wv.x + b.y * wv.y + b.z * wv.z + b.w * wv.w;
            }
            #pragma unroll
            for (int o = 16; o > 0; o >>= 1) {
                d0 += __shfl_xor_sync(0xffffffffu, d0, o);
                d1 += __shfl_xor_sync(0xffffffffu, d1, o);
            }
            d0 += bias; d1 += bias;

            const float m   = fmaxf(d0, d1);
            const float e0  = __expf(d0 - m);
            const float e1  = __expf(d1 - m);
            const float inv = 1.f / (e0 + e1);
            const float a0 = e0 * inv, a1 = e1 * inv;

            #pragma unroll
            for (int k = 0; k < PER_LANE; ++k) {
                const int idx = lane + 32 * k;
                const float4 a = s0[idx];
                const float4 b = s1[idx];
                float4 o4;
                o4.x = a0 * a.x + a1 * b.x;
                o4.y = a0 * a.y + a1 * b.y;
                o4.z = a0 * a.z + a1 * b.z;
                o4.w = a0 * a.w + a1 * b.w;
                po[idx] = o4;
            }
        } else {
            // ---- generic span: online softmax straight from global ----
            float m = -CUDART_INF_F;
            float denom = 0.f;
            float acc[PER_LANE * 4];
            #pragma unroll
            for (int k = 0; k < PER_LANE * 4; ++k) acc[k] = 0.f;

            for (int s = se.x; s < se.y; ++s) {
                const float4* __restrict__ p =
                    reinterpret_cast<const float4*>(emb + (size_t)s * D_DIM);
                float4 r[PER_LANE];
                float d = 0.f;
                #pragma unroll
                for (int k = 0; k < PER_LANE; ++k) {
                    const int idx = lane + 32 * k;
                    const float4 wv = reinterpret_cast<const float4*>(sw)[idx];
                    r[k] = p[idx];
                    d += r[k].x * wv.x + r[k].y * wv.y + r[k].z * wv.z + r[k].w * wv.w;
                }
                #pragma unroll
                for (int o = 16; o > 0; o >>= 1)
                    d += __shfl_xor_sync(0xffffffffu, d, o);
                d += bias;

                const float mn    = fmaxf(m, d);
                const float scale = __expf(m - mn);
                const float e     = __expf(d - mn);
                denom = denom * scale + e;
                #pragma unroll
                for (int k = 0; k < PER_LANE; ++k) {
                    acc[4*k+0] = acc[4*k+0] * scale + e * r[k].x;
                    acc[4*k+1] = acc[4*k+1] * scale + e * r[k].y;
                    acc[4*k+2] = acc[4*k+2] * scale + e * r[k].z;
                    acc[4*k+3] = acc[4*k+3] * scale + e * r[k].w;
                }
                m = mn;
            }
            const float inv = 1.f / denom;
            #pragma unroll
            for (int k = 0; k < PER_LANE; ++k) {
                float4 o4;
                o4.x = acc[4*k+0] * inv;
                o4.y = acc[4*k+1] * inv;
                o4.z = acc[4*k+2] * inv;
                o4.w = acc[4*k+3] * inv;
                po[lane + 32 * k] = o4;
            }
        }

        if (next >= n_words) break;
        word = next;
        se = se_n;
        stage ^= 1;
    }
}

extern "C" void kernel_launch(void* const* d_in, const int* in_sizes, int n_in,
                              void* d_out, int out_size)
{
    const float* emb    = (const float*)d_in[0];   // [n_subwords, 768] fp32
    const int*   offs   = (const int*)  d_in[1];   // [n_words, 2] int32
    const float* attn_w = (const float*)d_in[2];   // [768] fp32
    const float* attn_b = (const float*)d_in[3];   // scalar fp32
    float*       out    = (float*)d_out;           // [n_words, 768] fp32

    const int n_words = in_sizes[1] / 2;

    const int smem_bytes =
        (SW_FLOATS + WARPS_PB * 2 * BUF_FLOATS) * (int)sizeof(float);  // 101376

    cudaFuncSetAttribute(encoder_word_pool_kernel,
                         cudaFuncAttributeMaxDynamicSharedMemorySize, smem_bytes);

    int blocks = GRID_BLKS;
    const int max_blocks = (n_words + WARPS_PB - 1) / WARPS_PB;
    if (blocks > max_blocks) blocks = max_blocks;

    encoder_word_pool_kernel<<<blocks, THREADS_PB, smem_bytes>>>(
        emb, offs, attn_w, attn_b, out, n_words);
}